// round 12
// baseline (speedup 1.0000x reference)
#include <cuda_runtime.h>
#include <cuda_fp16.h>
#include <math.h>
#include <stdint.h>

#define VOCAB 50000
#define EMB   300
#define SEQ   80
#define HID   128
#define BATCH 4096

typedef unsigned long long ull;

// Scratch: projected embedding table P = emb @ Wxh (25.6 MB, L2-resident at use)
__device__ float g_P[VOCAB * HID];

__device__ __forceinline__ uint32_t su32(const void* p) {
    uint32_t a;
    asm("{ .reg .u64 t; cvta.to.shared.u64 t, %1; cvt.u32.u64 %0, t; }" : "=r"(a) : "l"(p));
    return a;
}
__device__ __forceinline__ float ftanh(float x) {
    float e = __expf(2.f * x);
    return 1.f - __fdividef(2.f, e + 1.f);
}
__device__ __forceinline__ uint32_t pkh(float a, float b) {
    __half2 h = __halves2half2(__float2half_rn(a), __float2half_rn(b));
    return *reinterpret_cast<uint32_t*>(&h);
}

// ---------------------------------------------------------------------------
// Kernel A: P[v][j] = sum_e emb[v][e] * Wxh[e][j]
// (exact R4-winner version: PTK=20, double-buffered, 1 sync/iter, grid=391)
// ---------------------------------------------------------------------------
#define PTK 20

__global__ __launch_bounds__(256) void proj_kernel(const float* __restrict__ emb,
                                                   const float* __restrict__ Wxh) {
    __shared__ float As[2][PTK][128];
    __shared__ float Bs[2][PTK][128];

    const int tid = threadIdx.x;
    const int v0  = blockIdx.x * 128;
    const int tr  = tid >> 4;
    const int tc  = tid & 15;

    float acc[8][8];
#pragma unroll
    for (int i = 0; i < 8; i++)
#pragma unroll
        for (int j = 0; j < 8; j++) acc[i][j] = 0.f;

    const bool isA = (tid < 128);
    int av = v0 + tid; if (av > VOCAB - 1) av = VOCAB - 1;
    const int t2   = tid - 128;
    const int brow = t2 >> 5;
    const int bcol = (t2 & 31) * 4;

    float4 pf[5];
#pragma unroll
    for (int q = 0; q < 5; q++) {
        if (isA) pf[q] = *(const float4*)&emb[(long)av * EMB + 0 + q * 4];
        else     pf[q] = *(const float4*)&Wxh[(0 + q * 4 + brow) * HID + bcol];
    }

    for (int it = 0; it < 15; it++) {
        const int pb = it & 1;
        if (isA) {
#pragma unroll
            for (int q = 0; q < 5; q++) {
                As[pb][q * 4 + 0][tid] = pf[q].x;
                As[pb][q * 4 + 1][tid] = pf[q].y;
                As[pb][q * 4 + 2][tid] = pf[q].z;
                As[pb][q * 4 + 3][tid] = pf[q].w;
            }
        } else {
#pragma unroll
            for (int q = 0; q < 5; q++)
                *(float4*)&Bs[pb][q * 4 + brow][bcol] = pf[q];
        }
        __syncthreads();

        if (it + 1 < 15) {
            const int e0 = (it + 1) * PTK;
#pragma unroll
            for (int q = 0; q < 5; q++) {
                if (isA) pf[q] = *(const float4*)&emb[(long)av * EMB + e0 + q * 4];
                else     pf[q] = *(const float4*)&Wxh[(e0 + q * 4 + brow) * HID + bcol];
            }
        }

#pragma unroll
        for (int k = 0; k < PTK; k++) {
            float a[8], b[8];
            *(float4*)&a[0] = *(const float4*)&As[pb][k][tr * 8];
            *(float4*)&a[4] = *(const float4*)&As[pb][k][tr * 8 + 4];
            *(float4*)&b[0] = *(const float4*)&Bs[pb][k][tc * 8];
            *(float4*)&b[4] = *(const float4*)&Bs[pb][k][tc * 8 + 4];
#pragma unroll
            for (int i = 0; i < 8; i++)
#pragma unroll
                for (int j = 0; j < 8; j++) acc[i][j] += a[i] * b[j];
        }
        __syncthreads();
    }

#pragma unroll
    for (int i = 0; i < 8; i++) {
        const int v = v0 + tr * 8 + i;
        if (v < VOCAB) {
            *(float4*)&g_P[(long)v * HID + tc * 8]     = *(float4*)&acc[i][0];
            *(float4*)&g_P[(long)v * HID + tc * 8 + 4] = *(float4*)&acc[i][4];
        }
    }
}

// ---------------------------------------------------------------------------
// Kernel B: tensor-core recurrence (R11 machinery) + two changes:
//  1. The two 16-row halves (wr=0: warps 0-3, wr=1: warps 4-7) are data-
//     independent -> per-half NAMED barriers (bar.sync wr+1, 128) instead of
//     __syncthreads, letting the halves' mma and tanh phases overlap.
//  2. Accumulator chains split: s=0..3 -> acc, s=4..7 -> acc2 (summed after),
//     doubling independent HMMA chains 4 -> 8. v[] no longer persists in
//     regs; epilogue reconstructs final h from the smem hi/lo buffers.
// ---------------------------------------------------------------------------
#define HPITCH 272          // bytes per h row (136 halves)
#define HSEG   8704         // 32 rows * 272

__global__ __launch_bounds__(256, 1) void rnn_tc_kernel(const int* __restrict__ x,
                                                        const float* __restrict__ Whh,
                                                        const float* __restrict__ bh,
                                                        const float* __restrict__ Wd,
                                                        const float* __restrict__ bd,
                                                        float* __restrict__ out) {
    extern __shared__ char smc[];
    float* Whh_sh = (float*)smc;
    int*   tok_sh = (int*)(smc + 65536);
    char*  hbase  = smc;
    float* red    = (float*)(smc + 34816);

    const int tid  = threadIdx.x;
    const int lane = tid & 31;
    const int wid  = tid >> 5;
    const int wr   = wid >> 2;       // half 0..1 (warps 0-3 / 4-7: contiguous threads)
    const int wc   = wid & 3;        // colgroup 0..3
    const int g    = lane >> 2;
    const int q    = lane & 3;
    const int b0   = blockIdx.x * 32;

    // ---- init: Whh fp32 + tokens ----
    {
        const float4* s = (const float4*)Whh;
        float4* d = (float4*)Whh_sh;
        for (int i = tid; i < HID * HID / 4; i += 256) d[i] = s[i];
        const int4* xs = (const int4*)(x + b0 * SEQ);
        int4* td = (int4*)tok_sh;
        for (int i = tid; i < 32 * SEQ / 4; i += 256) td[i] = xs[i];
    }
    __syncthreads();

    // ---- extract B fragments (hi/lo) into registers ----
    uint32_t Bh[8][4][2], Bl[8][4][2];
#pragma unroll
    for (int s = 0; s < 8; s++) {
        const int k0 = s * 16 + 2 * q;
#pragma unroll
        for (int n = 0; n < 4; n++) {
            const int nc = wc * 32 + n * 8 + g;
            float w00 = Whh_sh[(k0)     * HID + nc];
            float w01 = Whh_sh[(k0 + 1) * HID + nc];
            float w10 = Whh_sh[(k0 + 8) * HID + nc];
            float w11 = Whh_sh[(k0 + 9) * HID + nc];
            float h00 = __half2float(__float2half_rn(w00));
            float h01 = __half2float(__float2half_rn(w01));
            float h10 = __half2float(__float2half_rn(w10));
            float h11 = __half2float(__float2half_rn(w11));
            Bh[s][n][0] = pkh(h00, h01);
            Bh[s][n][1] = pkh(h10, h11);
            Bl[s][n][0] = pkh(w00 - h00, w01 - h01);
            Bl[s][n][1] = pkh(w10 - h10, w11 - h11);
        }
    }
    __syncthreads();   // Whh_sh region now free for h buffers

    float2 bh2[4];
#pragma unroll
    for (int n = 0; n < 4; n++)
        bh2[n] = *(const float2*)&bh[wc * 32 + n * 8 + 2 * q];

    const int rowA = wr * 16 + g;
    const int rowB = rowA + 8;
    const uint32_t smem_u32 = su32(smc);
    const uint32_t lm_off = (uint32_t)((wr * 16 + (lane & 15)) * HPITCH + (lane >> 4) * 16);
    uint32_t stA[4], stB[4];
#pragma unroll
    for (int n = 0; n < 4; n++) {
        const int col = wc * 32 + n * 8 + 2 * q;
        stA[n] = (uint32_t)(rowA * HPITCH + col * 2);
        stB[n] = (uint32_t)(rowB * HPITCH + col * 2);
    }

    // prefetch t=0 inputs
    float2 xp[2][4];
    {
        const int tkA = tok_sh[rowA * SEQ + 0];
        const int tkB = tok_sh[rowB * SEQ + 0];
#pragma unroll
        for (int n = 0; n < 4; n++) {
            xp[0][n] = *(const float2*)&g_P[tkA * HID + wc * 32 + n * 8 + 2 * q];
            xp[1][n] = *(const float2*)&g_P[tkB * HID + wc * 32 + n * 8 + 2 * q];
        }
    }

    for (int t = 0; t < SEQ; t++) {
        float acc[4][4], acc2[4][4];
#pragma unroll
        for (int n = 0; n < 4; n++) {
            acc[n][0] = xp[0][n].x + bh2[n].x;
            acc[n][1] = xp[0][n].y + bh2[n].y;
            acc[n][2] = xp[1][n].x + bh2[n].x;
            acc[n][3] = xp[1][n].y + bh2[n].y;
            acc2[n][0] = 0.f; acc2[n][1] = 0.f; acc2[n][2] = 0.f; acc2[n][3] = 0.f;
        }

        if (t + 1 < SEQ) {
            const int tkA = tok_sh[rowA * SEQ + t + 1];
            const int tkB = tok_sh[rowB * SEQ + t + 1];
#pragma unroll
            for (int n = 0; n < 4; n++) {
                xp[0][n] = *(const float2*)&g_P[tkA * HID + wc * 32 + n * 8 + 2 * q];
                xp[1][n] = *(const float2*)&g_P[tkB * HID + wc * 32 + n * 8 + 2 * q];
            }
        }

        if (t > 0) {
            const uint32_t hseg = smem_u32 + ((t + 1) & 1) * (2 * HSEG);

            auto do_s = [&](int s, float (&A)[4][4]) {
                uint32_t Ah[4], Al[4];
                asm volatile("ldmatrix.sync.aligned.m8n8.x4.shared.b16 {%0,%1,%2,%3}, [%4];"
                             : "=r"(Ah[0]), "=r"(Ah[1]), "=r"(Ah[2]), "=r"(Ah[3])
                             : "r"(hseg + lm_off + s * 32));
                asm volatile("ldmatrix.sync.aligned.m8n8.x4.shared.b16 {%0,%1,%2,%3}, [%4];"
                             : "=r"(Al[0]), "=r"(Al[1]), "=r"(Al[2]), "=r"(Al[3])
                             : "r"(hseg + HSEG + lm_off + s * 32));
#pragma unroll
                for (int n = 0; n < 4; n++) {
                    asm volatile(
                        "mma.sync.aligned.m16n8k16.row.col.f32.f16.f16.f32 "
                        "{%0,%1,%2,%3}, {%4,%5,%6,%7}, {%8,%9}, {%0,%1,%2,%3};"
                        : "+f"(A[n][0]), "+f"(A[n][1]), "+f"(A[n][2]), "+f"(A[n][3])
                        : "r"(Ah[0]), "r"(Ah[1]), "r"(Ah[2]), "r"(Ah[3]),
                          "r"(Bh[s][n][0]), "r"(Bh[s][n][1]));
                    asm volatile(
                        "mma.sync.aligned.m16n8k16.row.col.f32.f16.f16.f32 "
                        "{%0,%1,%2,%3}, {%4,%5,%6,%7}, {%8,%9}, {%0,%1,%2,%3};"
                        : "+f"(A[n][0]), "+f"(A[n][1]), "+f"(A[n][2]), "+f"(A[n][3])
                        : "r"(Ah[0]), "r"(Ah[1]), "r"(Ah[2]), "r"(Ah[3]),
                          "r"(Bl[s][n][0]), "r"(Bl[s][n][1]));
                    asm volatile(
                        "mma.sync.aligned.m16n8k16.row.col.f32.f16.f16.f32 "
                        "{%0,%1,%2,%3}, {%4,%5,%6,%7}, {%8,%9}, {%0,%1,%2,%3};"
                        : "+f"(A[n][0]), "+f"(A[n][1]), "+f"(A[n][2]), "+f"(A[n][3])
                        : "r"(Al[0]), "r"(Al[1]), "r"(Al[2]), "r"(Al[3]),
                          "r"(Bh[s][n][0]), "r"(Bh[s][n][1]));
                }
            };
#pragma unroll
            for (int s = 0; s < 4; s++) do_s(s, acc);
#pragma unroll
            for (int s = 4; s < 8; s++) do_s(s, acc2);

#pragma unroll
            for (int n = 0; n < 4; n++) {
                acc[n][0] += acc2[n][0]; acc[n][1] += acc2[n][1];
                acc[n][2] += acc2[n][2]; acc[n][3] += acc2[n][3];
            }
        }

        // tanh + hi/lo store to buf t&1
        {
            char* ws = hbase + (t & 1) * (2 * HSEG);
#pragma unroll
            for (int n = 0; n < 4; n++) {
                float v0 = ftanh(acc[n][0]);
                float v1 = ftanh(acc[n][1]);
                float v2 = ftanh(acc[n][2]);
                float v3 = ftanh(acc[n][3]);
                float h0 = __half2float(__float2half_rn(v0));
                float h1 = __half2float(__float2half_rn(v1));
                float h2 = __half2float(__float2half_rn(v2));
                float h3 = __half2float(__float2half_rn(v3));
                *(uint32_t*)(ws + stA[n])        = pkh(h0, h1);
                *(uint32_t*)(ws + HSEG + stA[n]) = pkh(v0 - h0, v1 - h1);
                *(uint32_t*)(ws + stB[n])        = pkh(h2, h3);
                *(uint32_t*)(ws + HSEG + stB[n]) = pkh(v2 - h2, v3 - h3);
            }
        }
        // per-half barrier: warps of half wr only (threads wr*128..+127)
        asm volatile("bar.sync %0, %1;" :: "r"(wr + 1), "r"(128) : "memory");
    }

    // ---- Dense(1) + sigmoid: reconstruct final h from smem hi/lo ----
    {
        const char* ws = hbase + ((SEQ - 1) & 1) * (2 * HSEG);
        float pA = 0.f, pB = 0.f;
#pragma unroll
        for (int n = 0; n < 4; n++) {
            const float2 wd2 = *(const float2*)&Wd[wc * 32 + n * 8 + 2 * q];
            __half2 hA = *(const __half2*)(ws + stA[n]);
            __half2 lA = *(const __half2*)(ws + HSEG + stA[n]);
            __half2 hB = *(const __half2*)(ws + stB[n]);
            __half2 lB = *(const __half2*)(ws + HSEG + stB[n]);
            pA += (__half2float(hA.x) + __half2float(lA.x)) * wd2.x
                + (__half2float(hA.y) + __half2float(lA.y)) * wd2.y;
            pB += (__half2float(hB.x) + __half2float(lB.x)) * wd2.x
                + (__half2float(hB.y) + __half2float(lB.y)) * wd2.y;
        }
        pA += __shfl_xor_sync(0xffffffff, pA, 1);
        pA += __shfl_xor_sync(0xffffffff, pA, 2);
        pB += __shfl_xor_sync(0xffffffff, pB, 1);
        pB += __shfl_xor_sync(0xffffffff, pB, 2);
        if (q == 0) {
            red[rowA * 4 + wc] = pA;
            red[rowB * 4 + wc] = pB;
        }
    }
    __syncthreads();
    if (tid < 32) {
        const float s = red[tid * 4] + red[tid * 4 + 1] + red[tid * 4 + 2]
                      + red[tid * 4 + 3] + bd[0];
        out[b0 + tid] = __fdividef(1.f, 1.f + __expf(-s));
    }
}

// ---------------------------------------------------------------------------
extern "C" void kernel_launch(void* const* d_in, const int* in_sizes, int n_in,
                              void* d_out, int out_size) {
    const int*   x   = (const int*)d_in[0];
    const float* emb = (const float*)d_in[1];
    const float* Wxh = (const float*)d_in[2];
    const float* Whh = (const float*)d_in[3];
    const float* bh  = (const float*)d_in[4];
    const float* Wd  = (const float*)d_in[5];
    const float* bd  = (const float*)d_in[6];
    float* out = (float*)d_out;

    proj_kernel<<<(VOCAB + 127) / 128, 256>>>(emb, Wxh);

    const int smem = 65536 + 32 * SEQ * 4;   // 75776 B
    cudaFuncSetAttribute(rnn_tc_kernel, cudaFuncAttributeMaxDynamicSharedMemorySize, smem);
    rnn_tc_kernel<<<BATCH / 32, 256, smem>>>(x, Whh, bh, Wd, bd, out);
}

// round 13
// speedup vs baseline: 1.0167x; 1.0167x over previous
#include <cuda_runtime.h>
#include <cuda_fp16.h>
#include <math.h>
#include <stdint.h>

#define VOCAB 50000
#define EMB   300
#define SEQ   80
#define HID   128
#define BATCH 4096

typedef unsigned long long ull;

// Scratch: projected embedding table P = emb @ Wxh (25.6 MB, L2-resident at use)
__device__ float g_P[VOCAB * HID];

__device__ __forceinline__ uint32_t su32(const void* p) {
    uint32_t a;
    asm("{ .reg .u64 t; cvta.to.shared.u64 t, %1; cvt.u32.u64 %0, t; }" : "=r"(a) : "l"(p));
    return a;
}
__device__ __forceinline__ float ftanh(float x) {
    float e = __expf(2.f * x);
    return 1.f - __fdividef(2.f, e + 1.f);
}
__device__ __forceinline__ uint32_t pkh(float a, float b) {
    __half2 h = __halves2half2(__float2half_rn(a), __float2half_rn(b));
    return *reinterpret_cast<uint32_t*>(&h);
}
// split (a,b) into packed fp16 hi + lo halves
__device__ __forceinline__ void cvt_hilo(float ax, float ay, uint32_t& hi, uint32_t& lo) {
    __half hx = __float2half_rn(ax), hy = __float2half_rn(ay);
    __half2 hh = __halves2half2(hx, hy);
    hi = *reinterpret_cast<uint32_t*>(&hh);
    __half lx = __float2half_rn(ax - __half2float(hx));
    __half ly = __float2half_rn(ay - __half2float(hy));
    __half2 ll = __halves2half2(lx, ly);
    lo = *reinterpret_cast<uint32_t*>(&ll);
}

// ---------------------------------------------------------------------------
// Kernel A (NEW): tensor-core proj. P[v][j] = sum_e emb[v][e] * Wxh[e][j].
// hi/lo fp16 split (3 mma products, ll dropped ~2^-22), R11 fragment maps.
// NO smem, NO barriers: lanes LDG fragment elements directly from global.
// Block = 128 thr = 4 warps; warp wc owns cols wc*32..+31, all 32 block rows
// (2 m16 tiles). grid = ceil(50000/32) = 1563. K = 300 in 19 chunks of 16
// (tail e>=300 zero-guarded). 1-chunk load-ahead double buffer.
// Fragment maps (g=lane>>2, q=lane&3):
//   A: a0=(g,2q|2q+1) a1=(g+8,..) a2=(g,2q+8|2q+9) a3=(g+8,2q+8..)
//   B: b0=(k=2q,2q+1; n=g)  b1=(k=2q+8,2q+9; n=g)
//   D: d0=(g,2q) d1=(g,2q+1) d2=(g+8,2q) d3=(g+8,2q+1)
// ---------------------------------------------------------------------------
#define PCHUNKS 19

__global__ __launch_bounds__(128) void proj_tc_kernel(const float* __restrict__ emb,
                                                      const float* __restrict__ Wxh) {
    const int tid  = threadIdx.x;
    const int lane = tid & 31;
    const int wc   = tid >> 5;        // warp 0..3 -> col group
    const int g    = lane >> 2;
    const int q    = lane & 3;
    const int rbase = blockIdx.x * 32;

    // clamped row byte-bases for 2 m-tiles (junk rows discarded at store)
    long rA[2], rB[2];
#pragma unroll
    for (int mt = 0; mt < 2; mt++) {
        int r0 = rbase + mt * 16 + g;
        int r1 = r0 + 8;
        if (r0 > VOCAB - 1) r0 = VOCAB - 1;
        if (r1 > VOCAB - 1) r1 = VOCAB - 1;
        rA[mt] = (long)r0 * EMB;
        rB[mt] = (long)r1 * EMB;
    }
    int ncol[4];
#pragma unroll
    for (int nf = 0; nf < 4; nf++) ncol[nf] = wc * 32 + nf * 8 + g;

    float acc[2][4][4];
#pragma unroll
    for (int mt = 0; mt < 2; mt++)
#pragma unroll
        for (int nf = 0; nf < 4; nf++)
#pragma unroll
            for (int d = 0; d < 4; d++) acc[mt][nf][d] = 0.f;

    // raw double buffers
    float2 a0[2][2], a1[2][2], a2[2][2], a3[2][2];   // [buf][mt]
    float  wv[2][4][4];                              // [buf][nf][0..3]

    auto load_chunk = [&](int ck, int buf) {
        const int k0 = ck * 16;
        const int eA = k0 + 2 * q;          // always < 300 (max 294)
        const int eB = eA + 8;              // may exceed 299 in tail chunk
        const bool vB = (eB < EMB);
#pragma unroll
        for (int mt = 0; mt < 2; mt++) {
            a0[buf][mt] = *(const float2*)(emb + rA[mt] + eA);
            a1[buf][mt] = *(const float2*)(emb + rB[mt] + eA);
            a2[buf][mt] = vB ? *(const float2*)(emb + rA[mt] + eB) : make_float2(0.f, 0.f);
            a3[buf][mt] = vB ? *(const float2*)(emb + rB[mt] + eB) : make_float2(0.f, 0.f);
        }
#pragma unroll
        for (int nf = 0; nf < 4; nf++) {
            wv[buf][nf][0] = Wxh[eA * HID + ncol[nf]];
            wv[buf][nf][1] = Wxh[(eA + 1) * HID + ncol[nf]];
            wv[buf][nf][2] = vB ? Wxh[eB * HID + ncol[nf]] : 0.f;
            wv[buf][nf][3] = vB ? Wxh[(eB + 1) * HID + ncol[nf]] : 0.f;
        }
    };

    load_chunk(0, 0);

#pragma unroll 1
    for (int ck = 0; ck < PCHUNKS; ck++) {
        const int cur = ck & 1;
        if (ck + 1 < PCHUNKS) load_chunk(ck + 1, cur ^ 1);

        // convert current chunk to hi/lo fragments
        uint32_t Ah[2][4], Al[2][4];
#pragma unroll
        for (int mt = 0; mt < 2; mt++) {
            cvt_hilo(a0[cur][mt].x, a0[cur][mt].y, Ah[mt][0], Al[mt][0]);
            cvt_hilo(a1[cur][mt].x, a1[cur][mt].y, Ah[mt][1], Al[mt][1]);
            cvt_hilo(a2[cur][mt].x, a2[cur][mt].y, Ah[mt][2], Al[mt][2]);
            cvt_hilo(a3[cur][mt].x, a3[cur][mt].y, Ah[mt][3], Al[mt][3]);
        }
        uint32_t Bh[4][2], Bl[4][2];
#pragma unroll
        for (int nf = 0; nf < 4; nf++) {
            cvt_hilo(wv[cur][nf][0], wv[cur][nf][1], Bh[nf][0], Bl[nf][0]);
            cvt_hilo(wv[cur][nf][2], wv[cur][nf][3], Bh[nf][1], Bl[nf][1]);
        }

#pragma unroll
        for (int mt = 0; mt < 2; mt++)
#pragma unroll
            for (int nf = 0; nf < 4; nf++) {
                float* A = acc[mt][nf];
                asm volatile(
                    "mma.sync.aligned.m16n8k16.row.col.f32.f16.f16.f32 "
                    "{%0,%1,%2,%3}, {%4,%5,%6,%7}, {%8,%9}, {%0,%1,%2,%3};"
                    : "+f"(A[0]), "+f"(A[1]), "+f"(A[2]), "+f"(A[3])
                    : "r"(Ah[mt][0]), "r"(Ah[mt][1]), "r"(Ah[mt][2]), "r"(Ah[mt][3]),
                      "r"(Bh[nf][0]), "r"(Bh[nf][1]));
                asm volatile(
                    "mma.sync.aligned.m16n8k16.row.col.f32.f16.f16.f32 "
                    "{%0,%1,%2,%3}, {%4,%5,%6,%7}, {%8,%9}, {%0,%1,%2,%3};"
                    : "+f"(A[0]), "+f"(A[1]), "+f"(A[2]), "+f"(A[3])
                    : "r"(Ah[mt][0]), "r"(Ah[mt][1]), "r"(Ah[mt][2]), "r"(Ah[mt][3]),
                      "r"(Bl[nf][0]), "r"(Bl[nf][1]));
                asm volatile(
                    "mma.sync.aligned.m16n8k16.row.col.f32.f16.f16.f32 "
                    "{%0,%1,%2,%3}, {%4,%5,%6,%7}, {%8,%9}, {%0,%1,%2,%3};"
                    : "+f"(A[0]), "+f"(A[1]), "+f"(A[2]), "+f"(A[3])
                    : "r"(Al[mt][0]), "r"(Al[mt][1]), "r"(Al[mt][2]), "r"(Al[mt][3]),
                      "r"(Bh[nf][0]), "r"(Bh[nf][1]));
            }
    }

    // store D
#pragma unroll
    for (int mt = 0; mt < 2; mt++) {
        const int r0 = rbase + mt * 16 + g;
        const int r1 = r0 + 8;
#pragma unroll
        for (int nf = 0; nf < 4; nf++) {
            const int n0 = wc * 32 + nf * 8 + 2 * q;
            if (r0 < VOCAB) {
                float2 v; v.x = acc[mt][nf][0]; v.y = acc[mt][nf][1];
                *(float2*)&g_P[(long)r0 * HID + n0] = v;
            }
            if (r1 < VOCAB) {
                float2 v; v.x = acc[mt][nf][2]; v.y = acc[mt][nf][3];
                *(float2*)&g_P[(long)r1 * HID + n0] = v;
            }
        }
    }
}

// ---------------------------------------------------------------------------
// Kernel B: tensor-core recurrence — R11 winner VERBATIM (136.5 us).
// ---------------------------------------------------------------------------
#define HPITCH 272          // bytes per h row (136 halves)
#define HSEG   8704         // 32 rows * 272

__global__ __launch_bounds__(256, 1) void rnn_tc_kernel(const int* __restrict__ x,
                                                        const float* __restrict__ Whh,
                                                        const float* __restrict__ bh,
                                                        const float* __restrict__ Wd,
                                                        const float* __restrict__ bd,
                                                        float* __restrict__ out) {
    extern __shared__ char smc[];
    float* Whh_sh = (float*)smc;
    int*   tok_sh = (int*)(smc + 65536);
    char*  hbase  = smc;
    float* red    = (float*)(smc + 34816);

    const int tid  = threadIdx.x;
    const int lane = tid & 31;
    const int wid  = tid >> 5;
    const int wr   = wid >> 2;
    const int wc   = wid & 3;
    const int g    = lane >> 2;
    const int q    = lane & 3;
    const int b0   = blockIdx.x * 32;

    {
        const float4* s = (const float4*)Whh;
        float4* d = (float4*)Whh_sh;
        for (int i = tid; i < HID * HID / 4; i += 256) d[i] = s[i];
        const int4* xs = (const int4*)(x + b0 * SEQ);
        int4* td = (int4*)tok_sh;
        for (int i = tid; i < 32 * SEQ / 4; i += 256) td[i] = xs[i];
    }
    __syncthreads();

    uint32_t Bh[8][4][2], Bl[8][4][2];
#pragma unroll
    for (int s = 0; s < 8; s++) {
        const int k0 = s * 16 + 2 * q;
#pragma unroll
        for (int n = 0; n < 4; n++) {
            const int nc = wc * 32 + n * 8 + g;
            float w00 = Whh_sh[(k0)     * HID + nc];
            float w01 = Whh_sh[(k0 + 1) * HID + nc];
            float w10 = Whh_sh[(k0 + 8) * HID + nc];
            float w11 = Whh_sh[(k0 + 9) * HID + nc];
            float h00 = __half2float(__float2half_rn(w00));
            float h01 = __half2float(__float2half_rn(w01));
            float h10 = __half2float(__float2half_rn(w10));
            float h11 = __half2float(__float2half_rn(w11));
            Bh[s][n][0] = pkh(h00, h01);
            Bh[s][n][1] = pkh(h10, h11);
            Bl[s][n][0] = pkh(w00 - h00, w01 - h01);
            Bl[s][n][1] = pkh(w10 - h10, w11 - h11);
        }
    }
    __syncthreads();

    float2 bh2[4];
#pragma unroll
    for (int n = 0; n < 4; n++)
        bh2[n] = *(const float2*)&bh[wc * 32 + n * 8 + 2 * q];

    const int rowA = wr * 16 + g;
    const int rowB = rowA + 8;
    const uint32_t smem_u32 = su32(smc);
    const uint32_t lm_off = (uint32_t)((wr * 16 + (lane & 15)) * HPITCH + (lane >> 4) * 16);
    uint32_t stA[4], stB[4];
#pragma unroll
    for (int n = 0; n < 4; n++) {
        const int col = wc * 32 + n * 8 + 2 * q;
        stA[n] = (uint32_t)(rowA * HPITCH + col * 2);
        stB[n] = (uint32_t)(rowB * HPITCH + col * 2);
    }

    float2 xp[2][4];
    {
        const int tkA = tok_sh[rowA * SEQ + 0];
        const int tkB = tok_sh[rowB * SEQ + 0];
#pragma unroll
        for (int n = 0; n < 4; n++) {
            xp[0][n] = *(const float2*)&g_P[tkA * HID + wc * 32 + n * 8 + 2 * q];
            xp[1][n] = *(const float2*)&g_P[tkB * HID + wc * 32 + n * 8 + 2 * q];
        }
    }

    float v[4][4];

    for (int t = 0; t < SEQ; t++) {
        float acc[4][4];
#pragma unroll
        for (int n = 0; n < 4; n++) {
            acc[n][0] = xp[0][n].x + bh2[n].x;
            acc[n][1] = xp[0][n].y + bh2[n].y;
            acc[n][2] = xp[1][n].x + bh2[n].x;
            acc[n][3] = xp[1][n].y + bh2[n].y;
        }

        if (t + 1 < SEQ) {
            const int tkA = tok_sh[rowA * SEQ + t + 1];
            const int tkB = tok_sh[rowB * SEQ + t + 1];
#pragma unroll
            for (int n = 0; n < 4; n++) {
                xp[0][n] = *(const float2*)&g_P[tkA * HID + wc * 32 + n * 8 + 2 * q];
                xp[1][n] = *(const float2*)&g_P[tkB * HID + wc * 32 + n * 8 + 2 * q];
            }
        }

        if (t > 0) {
            const uint32_t hseg = smem_u32 + ((t + 1) & 1) * (2 * HSEG);
#pragma unroll
            for (int s = 0; s < 8; s++) {
                uint32_t Ah[4], Al[4];
                asm volatile("ldmatrix.sync.aligned.m8n8.x4.shared.b16 {%0,%1,%2,%3}, [%4];"
                             : "=r"(Ah[0]), "=r"(Ah[1]), "=r"(Ah[2]), "=r"(Ah[3])
                             : "r"(hseg + lm_off + s * 32));
                asm volatile("ldmatrix.sync.aligned.m8n8.x4.shared.b16 {%0,%1,%2,%3}, [%4];"
                             : "=r"(Al[0]), "=r"(Al[1]), "=r"(Al[2]), "=r"(Al[3])
                             : "r"(hseg + HSEG + lm_off + s * 32));
#pragma unroll
                for (int n = 0; n < 4; n++) {
                    asm volatile(
                        "mma.sync.aligned.m16n8k16.row.col.f32.f16.f16.f32 "
                        "{%0,%1,%2,%3}, {%4,%5,%6,%7}, {%8,%9}, {%0,%1,%2,%3};"
                        : "+f"(acc[n][0]), "+f"(acc[n][1]), "+f"(acc[n][2]), "+f"(acc[n][3])
                        : "r"(Ah[0]), "r"(Ah[1]), "r"(Ah[2]), "r"(Ah[3]),
                          "r"(Bh[s][n][0]), "r"(Bh[s][n][1]));
                    asm volatile(
                        "mma.sync.aligned.m16n8k16.row.col.f32.f16.f16.f32 "
                        "{%0,%1,%2,%3}, {%4,%5,%6,%7}, {%8,%9}, {%0,%1,%2,%3};"
                        : "+f"(acc[n][0]), "+f"(acc[n][1]), "+f"(acc[n][2]), "+f"(acc[n][3])
                        : "r"(Ah[0]), "r"(Ah[1]), "r"(Ah[2]), "r"(Ah[3]),
                          "r"(Bl[s][n][0]), "r"(Bl[s][n][1]));
                    asm volatile(
                        "mma.sync.aligned.m16n8k16.row.col.f32.f16.f16.f32 "
                        "{%0,%1,%2,%3}, {%4,%5,%6,%7}, {%8,%9}, {%0,%1,%2,%3};"
                        : "+f"(acc[n][0]), "+f"(acc[n][1]), "+f"(acc[n][2]), "+f"(acc[n][3])
                        : "r"(Al[0]), "r"(Al[1]), "r"(Al[2]), "r"(Al[3]),
                          "r"(Bh[s][n][0]), "r"(Bh[s][n][1]));
                }
            }
        }

#pragma unroll
        for (int n = 0; n < 4; n++)
#pragma unroll
            for (int d = 0; d < 4; d++)
                v[n][d] = ftanh(acc[n][d]);

        {
            char* ws = hbase + (t & 1) * (2 * HSEG);
#pragma unroll
            for (int n = 0; n < 4; n++) {
                float h0 = __half2float(__float2half_rn(v[n][0]));
                float h1 = __half2float(__float2half_rn(v[n][1]));
                float h2 = __half2float(__float2half_rn(v[n][2]));
                float h3 = __half2float(__float2half_rn(v[n][3]));
                *(uint32_t*)(ws + stA[n])        = pkh(h0, h1);
                *(uint32_t*)(ws + HSEG + stA[n]) = pkh(v[n][0] - h0, v[n][1] - h1);
                *(uint32_t*)(ws + stB[n])        = pkh(h2, h3);
                *(uint32_t*)(ws + HSEG + stB[n]) = pkh(v[n][2] - h2, v[n][3] - h3);
            }
        }
        __syncthreads();
    }

    float pA = 0.f, pB = 0.f;
#pragma unroll
    for (int n = 0; n < 4; n++) {
        const float2 wd2 = *(const float2*)&Wd[wc * 32 + n * 8 + 2 * q];
        pA += v[n][0] * wd2.x + v[n][1] * wd2.y;
        pB += v[n][2] * wd2.x + v[n][3] * wd2.y;
    }
    pA += __shfl_xor_sync(0xffffffff, pA, 1);
    pA += __shfl_xor_sync(0xffffffff, pA, 2);
    pB += __shfl_xor_sync(0xffffffff, pB, 1);
    pB += __shfl_xor_sync(0xffffffff, pB, 2);
    if (q == 0) {
        red[rowA * 4 + wc] = pA;
        red[rowB * 4 + wc] = pB;
    }
    __syncthreads();
    if (tid < 32) {
        const float s = red[tid * 4] + red[tid * 4 + 1] + red[tid * 4 + 2]
                      + red[tid * 4 + 3] + bd[0];
        out[b0 + tid] = __fdividef(1.f, 1.f + __expf(-s));
    }
}

// ---------------------------------------------------------------------------
extern "C" void kernel_launch(void* const* d_in, const int* in_sizes, int n_in,
                              void* d_out, int out_size) {
    const int*   x   = (const int*)d_in[0];
    const float* emb = (const float*)d_in[1];
    const float* Wxh = (const float*)d_in[2];
    const float* Whh = (const float*)d_in[3];
    const float* bh  = (const float*)d_in[4];
    const float* Wd  = (const float*)d_in[5];
    const float* bd  = (const float*)d_in[6];
    float* out = (float*)d_out;

    proj_tc_kernel<<<(VOCAB + 31) / 32, 128>>>(emb, Wxh);

    const int smem = 65536 + 32 * SEQ * 4;   // 75776 B
    cudaFuncSetAttribute(rnn_tc_kernel, cudaFuncAttributeMaxDynamicSharedMemorySize, smem);
    rnn_tc_kernel<<<BATCH / 32, 256, smem>>>(x, Whh, bh, Wd, bd, out);
}

// round 14
// speedup vs baseline: 1.0468x; 1.0296x over previous
#include <cuda_runtime.h>
#include <cuda_fp16.h>
#include <math.h>
#include <stdint.h>

#define VOCAB 50000
#define EMB   300
#define SEQ   80
#define HID   128
#define BATCH 4096

typedef unsigned long long ull;

// Scratch: projected embedding table P = emb @ Wxh (25.6 MB, L2-resident at use)
__device__ float g_P[VOCAB * HID];

__device__ __forceinline__ uint32_t su32(const void* p) {
    uint32_t a;
    asm("{ .reg .u64 t; cvta.to.shared.u64 t, %1; cvt.u32.u64 %0, t; }" : "=r"(a) : "l"(p));
    return a;
}
__device__ __forceinline__ float ftanh(float x) {
    float e = __expf(2.f * x);
    return 1.f - __fdividef(2.f, e + 1.f);
}
__device__ __forceinline__ uint32_t pkh(float a, float b) {
    __half2 h = __halves2half2(__float2half_rn(a), __float2half_rn(b));
    return *reinterpret_cast<uint32_t*>(&h);
}

// ---------------------------------------------------------------------------
// Kernel A: P[v][j] = sum_e emb[v][e] * Wxh[e][j]
// (proven R4 SIMT version: PTK=20, double-buffered, 1 sync/iter, grid=391)
// ---------------------------------------------------------------------------
#define PTK 20

__global__ __launch_bounds__(256) void proj_kernel(const float* __restrict__ emb,
                                                   const float* __restrict__ Wxh) {
    __shared__ float As[2][PTK][128];
    __shared__ float Bs[2][PTK][128];

    const int tid = threadIdx.x;
    const int v0  = blockIdx.x * 128;
    const int tr  = tid >> 4;
    const int tc  = tid & 15;

    float acc[8][8];
#pragma unroll
    for (int i = 0; i < 8; i++)
#pragma unroll
        for (int j = 0; j < 8; j++) acc[i][j] = 0.f;

    const bool isA = (tid < 128);
    int av = v0 + tid; if (av > VOCAB - 1) av = VOCAB - 1;
    const int t2   = tid - 128;
    const int brow = t2 >> 5;
    const int bcol = (t2 & 31) * 4;

    float4 pf[5];
#pragma unroll
    for (int q = 0; q < 5; q++) {
        if (isA) pf[q] = *(const float4*)&emb[(long)av * EMB + 0 + q * 4];
        else     pf[q] = *(const float4*)&Wxh[(0 + q * 4 + brow) * HID + bcol];
    }

    for (int it = 0; it < 15; it++) {
        const int pb = it & 1;
        if (isA) {
#pragma unroll
            for (int q = 0; q < 5; q++) {
                As[pb][q * 4 + 0][tid] = pf[q].x;
                As[pb][q * 4 + 1][tid] = pf[q].y;
                As[pb][q * 4 + 2][tid] = pf[q].z;
                As[pb][q * 4 + 3][tid] = pf[q].w;
            }
        } else {
#pragma unroll
            for (int q = 0; q < 5; q++)
                *(float4*)&Bs[pb][q * 4 + brow][bcol] = pf[q];
        }
        __syncthreads();

        if (it + 1 < 15) {
            const int e0 = (it + 1) * PTK;
#pragma unroll
            for (int q = 0; q < 5; q++) {
                if (isA) pf[q] = *(const float4*)&emb[(long)av * EMB + e0 + q * 4];
                else     pf[q] = *(const float4*)&Wxh[(e0 + q * 4 + brow) * HID + bcol];
            }
        }

#pragma unroll
        for (int k = 0; k < PTK; k++) {
            float a[8], b[8];
            *(float4*)&a[0] = *(const float4*)&As[pb][k][tr * 8];
            *(float4*)&a[4] = *(const float4*)&As[pb][k][tr * 8 + 4];
            *(float4*)&b[0] = *(const float4*)&Bs[pb][k][tc * 8];
            *(float4*)&b[4] = *(const float4*)&Bs[pb][k][tc * 8 + 4];
#pragma unroll
            for (int i = 0; i < 8; i++)
#pragma unroll
                for (int j = 0; j < 8; j++) acc[i][j] += a[i] * b[j];
        }
        __syncthreads();
    }

#pragma unroll
    for (int i = 0; i < 8; i++) {
        const int v = v0 + tr * 8 + i;
        if (v < VOCAB) {
            *(float4*)&g_P[(long)v * HID + tc * 8]     = *(float4*)&acc[i][0];
            *(float4*)&g_P[(long)v * HID + tc * 8 + 4] = *(float4*)&acc[i][4];
        }
    }
}

// ---------------------------------------------------------------------------
// Kernel B: tensor-core recurrence — R11 machinery reshaped to 512 threads /
// 16 warps (4 per SMSP) for latency hiding. Warp(wr = wid>>3, wc = wid&7):
// rows wr*16..+15, cols wc*16..+15 (nf = 0..1). Per warp per step:
// 16 ldmatrix + 48 HMMA + 8 tanh. All fragment maps / layout / hi-lo split
// identical to the R11 winner; only column-group indexing changed.
// ---------------------------------------------------------------------------
#define HPITCH 272          // bytes per h row (136 halves)
#define HSEG   8704         // 32 rows * 272

__global__ __launch_bounds__(512, 1) void rnn_tc_kernel(const int* __restrict__ x,
                                                        const float* __restrict__ Whh,
                                                        const float* __restrict__ bh,
                                                        const float* __restrict__ Wd,
                                                        const float* __restrict__ bd,
                                                        float* __restrict__ out) {
    extern __shared__ char smc[];
    float* Whh_sh = (float*)smc;
    int*   tok_sh = (int*)(smc + 65536);
    char*  hbase  = smc;
    float* red    = (float*)(smc + 34816);   // 32 rows x 8 wc

    const int tid  = threadIdx.x;
    const int lane = tid & 31;
    const int wid  = tid >> 5;
    const int wr   = wid >> 3;       // 0..1 row half
    const int wc   = wid & 7;        // 0..7 col group (16 cols)
    const int g    = lane >> 2;
    const int q    = lane & 3;
    const int b0   = blockIdx.x * 32;

    // ---- init: Whh fp32 + tokens ----
    {
        const float4* s = (const float4*)Whh;
        float4* d = (float4*)Whh_sh;
        for (int i = tid; i < HID * HID / 4; i += 512) d[i] = s[i];
        const int4* xs = (const int4*)(x + b0 * SEQ);
        int4* td = (int4*)tok_sh;
        for (int i = tid; i < 32 * SEQ / 4; i += 512) td[i] = xs[i];
    }
    __syncthreads();

    // ---- extract B fragments (hi/lo) into registers ----
    uint32_t Bh[8][2][2], Bl[8][2][2];
#pragma unroll
    for (int s = 0; s < 8; s++) {
        const int k0 = s * 16 + 2 * q;
#pragma unroll
        for (int n = 0; n < 2; n++) {
            const int nc = wc * 16 + n * 8 + g;
            float w00 = Whh_sh[(k0)     * HID + nc];
            float w01 = Whh_sh[(k0 + 1) * HID + nc];
            float w10 = Whh_sh[(k0 + 8) * HID + nc];
            float w11 = Whh_sh[(k0 + 9) * HID + nc];
            float h00 = __half2float(__float2half_rn(w00));
            float h01 = __half2float(__float2half_rn(w01));
            float h10 = __half2float(__float2half_rn(w10));
            float h11 = __half2float(__float2half_rn(w11));
            Bh[s][n][0] = pkh(h00, h01);
            Bh[s][n][1] = pkh(h10, h11);
            Bl[s][n][0] = pkh(w00 - h00, w01 - h01);
            Bl[s][n][1] = pkh(w10 - h10, w11 - h11);
        }
    }
    __syncthreads();   // Whh_sh region now free for h buffers

    float2 bh2[2];
#pragma unroll
    for (int n = 0; n < 2; n++)
        bh2[n] = *(const float2*)&bh[wc * 16 + n * 8 + 2 * q];

    const int rowA = wr * 16 + g;
    const int rowB = rowA + 8;
    const uint32_t smem_u32 = su32(smc);
    const uint32_t lm_off = (uint32_t)((wr * 16 + (lane & 15)) * HPITCH + (lane >> 4) * 16);
    uint32_t stA[2], stB[2];
#pragma unroll
    for (int n = 0; n < 2; n++) {
        const int col = wc * 16 + n * 8 + 2 * q;
        stA[n] = (uint32_t)(rowA * HPITCH + col * 2);
        stB[n] = (uint32_t)(rowB * HPITCH + col * 2);
    }

    // prefetch t=0 inputs
    float2 xp[2][2];
    {
        const int tkA = tok_sh[rowA * SEQ + 0];
        const int tkB = tok_sh[rowB * SEQ + 0];
#pragma unroll
        for (int n = 0; n < 2; n++) {
            xp[0][n] = *(const float2*)&g_P[tkA * HID + wc * 16 + n * 8 + 2 * q];
            xp[1][n] = *(const float2*)&g_P[tkB * HID + wc * 16 + n * 8 + 2 * q];
        }
    }

    float v[2][4];   // tanh values, persist to epilogue

    for (int t = 0; t < SEQ; t++) {
        float acc[2][4];
#pragma unroll
        for (int n = 0; n < 2; n++) {
            acc[n][0] = xp[0][n].x + bh2[n].x;
            acc[n][1] = xp[0][n].y + bh2[n].y;
            acc[n][2] = xp[1][n].x + bh2[n].x;
            acc[n][3] = xp[1][n].y + bh2[n].y;
        }

        if (t + 1 < SEQ) {
            const int tkA = tok_sh[rowA * SEQ + t + 1];
            const int tkB = tok_sh[rowB * SEQ + t + 1];
#pragma unroll
            for (int n = 0; n < 2; n++) {
                xp[0][n] = *(const float2*)&g_P[tkA * HID + wc * 16 + n * 8 + 2 * q];
                xp[1][n] = *(const float2*)&g_P[tkB * HID + wc * 16 + n * 8 + 2 * q];
            }
        }

        if (t > 0) {
            const uint32_t hseg = smem_u32 + ((t + 1) & 1) * (2 * HSEG);
#pragma unroll
            for (int s = 0; s < 8; s++) {
                uint32_t Ah[4], Al[4];
                asm volatile("ldmatrix.sync.aligned.m8n8.x4.shared.b16 {%0,%1,%2,%3}, [%4];"
                             : "=r"(Ah[0]), "=r"(Ah[1]), "=r"(Ah[2]), "=r"(Ah[3])
                             : "r"(hseg + lm_off + s * 32));
                asm volatile("ldmatrix.sync.aligned.m8n8.x4.shared.b16 {%0,%1,%2,%3}, [%4];"
                             : "=r"(Al[0]), "=r"(Al[1]), "=r"(Al[2]), "=r"(Al[3])
                             : "r"(hseg + HSEG + lm_off + s * 32));
#pragma unroll
                for (int n = 0; n < 2; n++) {
                    asm volatile(
                        "mma.sync.aligned.m16n8k16.row.col.f32.f16.f16.f32 "
                        "{%0,%1,%2,%3}, {%4,%5,%6,%7}, {%8,%9}, {%0,%1,%2,%3};"
                        : "+f"(acc[n][0]), "+f"(acc[n][1]), "+f"(acc[n][2]), "+f"(acc[n][3])
                        : "r"(Ah[0]), "r"(Ah[1]), "r"(Ah[2]), "r"(Ah[3]),
                          "r"(Bh[s][n][0]), "r"(Bh[s][n][1]));
                    asm volatile(
                        "mma.sync.aligned.m16n8k16.row.col.f32.f16.f16.f32 "
                        "{%0,%1,%2,%3}, {%4,%5,%6,%7}, {%8,%9}, {%0,%1,%2,%3};"
                        : "+f"(acc[n][0]), "+f"(acc[n][1]), "+f"(acc[n][2]), "+f"(acc[n][3])
                        : "r"(Ah[0]), "r"(Ah[1]), "r"(Ah[2]), "r"(Ah[3]),
                          "r"(Bl[s][n][0]), "r"(Bl[s][n][1]));
                    asm volatile(
                        "mma.sync.aligned.m16n8k16.row.col.f32.f16.f16.f32 "
                        "{%0,%1,%2,%3}, {%4,%5,%6,%7}, {%8,%9}, {%0,%1,%2,%3};"
                        : "+f"(acc[n][0]), "+f"(acc[n][1]), "+f"(acc[n][2]), "+f"(acc[n][3])
                        : "r"(Al[0]), "r"(Al[1]), "r"(Al[2]), "r"(Al[3]),
                          "r"(Bh[s][n][0]), "r"(Bh[s][n][1]));
                }
            }
        }

        // tanh
#pragma unroll
        for (int n = 0; n < 2; n++)
#pragma unroll
            for (int d = 0; d < 4; d++)
                v[n][d] = ftanh(acc[n][d]);

        // store h(t) hi/lo to buf t&1
        {
            char* ws = hbase + (t & 1) * (2 * HSEG);
#pragma unroll
            for (int n = 0; n < 2; n++) {
                float h0 = __half2float(__float2half_rn(v[n][0]));
                float h1 = __half2float(__float2half_rn(v[n][1]));
                float h2 = __half2float(__float2half_rn(v[n][2]));
                float h3 = __half2float(__float2half_rn(v[n][3]));
                *(uint32_t*)(ws + stA[n])        = pkh(h0, h1);
                *(uint32_t*)(ws + HSEG + stA[n]) = pkh(v[n][0] - h0, v[n][1] - h1);
                *(uint32_t*)(ws + stB[n])        = pkh(h2, h3);
                *(uint32_t*)(ws + HSEG + stB[n]) = pkh(v[n][2] - h2, v[n][3] - h3);
            }
        }
        __syncthreads();
    }

    // ---- Dense(1) + sigmoid ----
    float pA = 0.f, pB = 0.f;
#pragma unroll
    for (int n = 0; n < 2; n++) {
        const float2 wd2 = *(const float2*)&Wd[wc * 16 + n * 8 + 2 * q];
        pA += v[n][0] * wd2.x + v[n][1] * wd2.y;
        pB += v[n][2] * wd2.x + v[n][3] * wd2.y;
    }
    pA += __shfl_xor_sync(0xffffffff, pA, 1);
    pA += __shfl_xor_sync(0xffffffff, pA, 2);
    pB += __shfl_xor_sync(0xffffffff, pB, 1);
    pB += __shfl_xor_sync(0xffffffff, pB, 2);
    if (q == 0) {
        red[rowA * 8 + wc] = pA;
        red[rowB * 8 + wc] = pB;
    }
    __syncthreads();
    if (tid < 32) {
        float s = bd[0];
#pragma unroll
        for (int c = 0; c < 8; c++) s += red[tid * 8 + c];
        out[b0 + tid] = __fdividef(1.f, 1.f + __expf(-s));
    }
}

// ---------------------------------------------------------------------------
extern "C" void kernel_launch(void* const* d_in, const int* in_sizes, int n_in,
                              void* d_out, int out_size) {
    const int*   x   = (const int*)d_in[0];
    const float* emb = (const float*)d_in[1];
    const float* Wxh = (const float*)d_in[2];
    const float* Whh = (const float*)d_in[3];
    const float* bh  = (const float*)d_in[4];
    const float* Wd  = (const float*)d_in[5];
    const float* bd  = (const float*)d_in[6];
    float* out = (float*)d_out;

    proj_kernel<<<(VOCAB + 127) / 128, 256>>>(emb, Wxh);

    const int smem = 65536 + 32 * SEQ * 4;   // 75776 B
    cudaFuncSetAttribute(rnn_tc_kernel, cudaFuncAttributeMaxDynamicSharedMemorySize, smem);
    rnn_tc_kernel<<<BATCH / 32, 512, smem>>>(x, Whh, bh, Wd, bd, out);
}

// round 15
// speedup vs baseline: 1.0862x; 1.0376x over previous
#include <cuda_runtime.h>
#include <cuda_fp16.h>
#include <math.h>
#include <stdint.h>

#define VOCAB 50000
#define EMB   300
#define SEQ   80
#define HID   128
#define BATCH 4096

typedef unsigned long long ull;

// Scratch: projected embedding table P = emb @ Wxh (25.6 MB, L2-resident at use)
__device__ float g_P[VOCAB * HID];

__device__ __forceinline__ uint32_t su32(const void* p) {
    uint32_t a;
    asm("{ .reg .u64 t; cvta.to.shared.u64 t, %1; cvt.u32.u64 %0, t; }" : "=r"(a) : "l"(p));
    return a;
}
__device__ __forceinline__ float ftanh(float x) {
    float e = __expf(2.f * x);
    return 1.f - __fdividef(2.f, e + 1.f);
}
__device__ __forceinline__ uint32_t pkh(float a, float b) {
    __half2 h = __halves2half2(__float2half_rn(a), __float2half_rn(b));
    return *reinterpret_cast<uint32_t*>(&h);
}

// ---------------------------------------------------------------------------
// Kernel A: P[v][j] = sum_e emb[v][e] * Wxh[e][j]
// (proven R4 SIMT version: PTK=20, double-buffered, 1 sync/iter, grid=391)
// ---------------------------------------------------------------------------
#define PTK 20

__global__ __launch_bounds__(256) void proj_kernel(const float* __restrict__ emb,
                                                   const float* __restrict__ Wxh) {
    __shared__ float As[2][PTK][128];
    __shared__ float Bs[2][PTK][128];

    const int tid = threadIdx.x;
    const int v0  = blockIdx.x * 128;
    const int tr  = tid >> 4;
    const int tc  = tid & 15;

    float acc[8][8];
#pragma unroll
    for (int i = 0; i < 8; i++)
#pragma unroll
        for (int j = 0; j < 8; j++) acc[i][j] = 0.f;

    const bool isA = (tid < 128);
    int av = v0 + tid; if (av > VOCAB - 1) av = VOCAB - 1;
    const int t2   = tid - 128;
    const int brow = t2 >> 5;
    const int bcol = (t2 & 31) * 4;

    float4 pf[5];
#pragma unroll
    for (int q = 0; q < 5; q++) {
        if (isA) pf[q] = *(const float4*)&emb[(long)av * EMB + 0 + q * 4];
        else     pf[q] = *(const float4*)&Wxh[(0 + q * 4 + brow) * HID + bcol];
    }

    for (int it = 0; it < 15; it++) {
        const int pb = it & 1;
        if (isA) {
#pragma unroll
            for (int q = 0; q < 5; q++) {
                As[pb][q * 4 + 0][tid] = pf[q].x;
                As[pb][q * 4 + 1][tid] = pf[q].y;
                As[pb][q * 4 + 2][tid] = pf[q].z;
                As[pb][q * 4 + 3][tid] = pf[q].w;
            }
        } else {
#pragma unroll
            for (int q = 0; q < 5; q++)
                *(float4*)&Bs[pb][q * 4 + brow][bcol] = pf[q];
        }
        __syncthreads();

        if (it + 1 < 15) {
            const int e0 = (it + 1) * PTK;
#pragma unroll
            for (int q = 0; q < 5; q++) {
                if (isA) pf[q] = *(const float4*)&emb[(long)av * EMB + e0 + q * 4];
                else     pf[q] = *(const float4*)&Wxh[(e0 + q * 4 + brow) * HID + bcol];
            }
        }

#pragma unroll
        for (int k = 0; k < PTK; k++) {
            float a[8], b[8];
            *(float4*)&a[0] = *(const float4*)&As[pb][k][tr * 8];
            *(float4*)&a[4] = *(const float4*)&As[pb][k][tr * 8 + 4];
            *(float4*)&b[0] = *(const float4*)&Bs[pb][k][tc * 8];
            *(float4*)&b[4] = *(const float4*)&Bs[pb][k][tc * 8 + 4];
#pragma unroll
            for (int i = 0; i < 8; i++)
#pragma unroll
                for (int j = 0; j < 8; j++) acc[i][j] += a[i] * b[j];
        }
        __syncthreads();
    }

#pragma unroll
    for (int i = 0; i < 8; i++) {
        const int v = v0 + tr * 8 + i;
        if (v < VOCAB) {
            *(float4*)&g_P[(long)v * HID + tc * 8]     = *(float4*)&acc[i][0];
            *(float4*)&g_P[(long)v * HID + tc * 8 + 4] = *(float4*)&acc[i][4];
        }
    }
}

// ---------------------------------------------------------------------------
// Kernel B: tensor-core recurrence — R14 machinery shrunk to 16-row blocks so
// TWO independent blocks co-reside per SM (separate __syncthreads domains ->
// one block's mma overlaps the other's tanh/store/barrier).
// grid=256, 256 threads = 8 warps, warp wc = 0..7 owns cols wc*16..+15,
// all 16 rows. Fragment maps / layout / hi-lo split identical to R14.
// smem 70656 B -> 2 blocks/SM (141 KB).
// ---------------------------------------------------------------------------
#define HPITCH 272          // bytes per h row (136 halves)
#define HSEG16 4352         // 16 rows * 272
// smem: [0,17408) h bufs: b0_hi@0 b0_lo@4352 b1_hi@8704 b1_lo@13056
//       [17408,17920) red[16][8]
//       [65536,70656) tok  (Whh fp32 occupies [0,65536) during init only)

__global__ __launch_bounds__(256, 2) void rnn_tc_kernel(const int* __restrict__ x,
                                                        const float* __restrict__ Whh,
                                                        const float* __restrict__ bh,
                                                        const float* __restrict__ Wd,
                                                        const float* __restrict__ bd,
                                                        float* __restrict__ out) {
    extern __shared__ char smc[];
    float* Whh_sh = (float*)smc;
    int*   tok_sh = (int*)(smc + 65536);
    char*  hbase  = smc;
    float* red    = (float*)(smc + 17408);   // 16 rows x 8 wc

    const int tid  = threadIdx.x;
    const int lane = tid & 31;
    const int wc   = tid >> 5;       // 0..7 col group (16 cols)
    const int g    = lane >> 2;
    const int q    = lane & 3;
    const int b0   = blockIdx.x * 16;

    // ---- init: Whh fp32 + tokens ----
    {
        const float4* s = (const float4*)Whh;
        float4* d = (float4*)Whh_sh;
        for (int i = tid; i < HID * HID / 4; i += 256) d[i] = s[i];
        const int4* xs = (const int4*)(x + b0 * SEQ);
        int4* td = (int4*)tok_sh;
        for (int i = tid; i < 16 * SEQ / 4; i += 256) td[i] = xs[i];
    }
    __syncthreads();

    // ---- extract B fragments (hi/lo) into registers ----
    uint32_t Bh[8][2][2], Bl[8][2][2];
#pragma unroll
    for (int s = 0; s < 8; s++) {
        const int k0 = s * 16 + 2 * q;
#pragma unroll
        for (int n = 0; n < 2; n++) {
            const int nc = wc * 16 + n * 8 + g;
            float w00 = Whh_sh[(k0)     * HID + nc];
            float w01 = Whh_sh[(k0 + 1) * HID + nc];
            float w10 = Whh_sh[(k0 + 8) * HID + nc];
            float w11 = Whh_sh[(k0 + 9) * HID + nc];
            float h00 = __half2float(__float2half_rn(w00));
            float h01 = __half2float(__float2half_rn(w01));
            float h10 = __half2float(__float2half_rn(w10));
            float h11 = __half2float(__float2half_rn(w11));
            Bh[s][n][0] = pkh(h00, h01);
            Bh[s][n][1] = pkh(h10, h11);
            Bl[s][n][0] = pkh(w00 - h00, w01 - h01);
            Bl[s][n][1] = pkh(w10 - h10, w11 - h11);
        }
    }
    __syncthreads();   // Whh_sh region now free for h buffers

    float2 bh2[2];
#pragma unroll
    for (int n = 0; n < 2; n++)
        bh2[n] = *(const float2*)&bh[wc * 16 + n * 8 + 2 * q];

    const int rowA = g;              // 0..7
    const int rowB = g + 8;          // 8..15
    const uint32_t smem_u32 = su32(smc);
    const uint32_t lm_off = (uint32_t)((lane & 15) * HPITCH + (lane >> 4) * 16);
    uint32_t stA[2], stB[2];
#pragma unroll
    for (int n = 0; n < 2; n++) {
        const int col = wc * 16 + n * 8 + 2 * q;
        stA[n] = (uint32_t)(rowA * HPITCH + col * 2);
        stB[n] = (uint32_t)(rowB * HPITCH + col * 2);
    }

    // prefetch t=0 inputs
    float2 xp[2][2];
    {
        const int tkA = tok_sh[rowA * SEQ + 0];
        const int tkB = tok_sh[rowB * SEQ + 0];
#pragma unroll
        for (int n = 0; n < 2; n++) {
            xp[0][n] = *(const float2*)&g_P[tkA * HID + wc * 16 + n * 8 + 2 * q];
            xp[1][n] = *(const float2*)&g_P[tkB * HID + wc * 16 + n * 8 + 2 * q];
        }
    }

    float v[2][4];   // tanh values, persist to epilogue

    for (int t = 0; t < SEQ; t++) {
        float acc[2][4];
#pragma unroll
        for (int n = 0; n < 2; n++) {
            acc[n][0] = xp[0][n].x + bh2[n].x;
            acc[n][1] = xp[0][n].y + bh2[n].y;
            acc[n][2] = xp[1][n].x + bh2[n].x;
            acc[n][3] = xp[1][n].y + bh2[n].y;
        }

        if (t + 1 < SEQ) {
            const int tkA = tok_sh[rowA * SEQ + t + 1];
            const int tkB = tok_sh[rowB * SEQ + t + 1];
#pragma unroll
            for (int n = 0; n < 2; n++) {
                xp[0][n] = *(const float2*)&g_P[tkA * HID + wc * 16 + n * 8 + 2 * q];
                xp[1][n] = *(const float2*)&g_P[tkB * HID + wc * 16 + n * 8 + 2 * q];
            }
        }

        if (t > 0) {
            const uint32_t hseg = smem_u32 + ((t + 1) & 1) * (2 * HSEG16);
#pragma unroll
            for (int s = 0; s < 8; s++) {
                uint32_t Ah[4], Al[4];
                asm volatile("ldmatrix.sync.aligned.m8n8.x4.shared.b16 {%0,%1,%2,%3}, [%4];"
                             : "=r"(Ah[0]), "=r"(Ah[1]), "=r"(Ah[2]), "=r"(Ah[3])
                             : "r"(hseg + lm_off + s * 32));
                asm volatile("ldmatrix.sync.aligned.m8n8.x4.shared.b16 {%0,%1,%2,%3}, [%4];"
                             : "=r"(Al[0]), "=r"(Al[1]), "=r"(Al[2]), "=r"(Al[3])
                             : "r"(hseg + HSEG16 + lm_off + s * 32));
#pragma unroll
                for (int n = 0; n < 2; n++) {
                    asm volatile(
                        "mma.sync.aligned.m16n8k16.row.col.f32.f16.f16.f32 "
                        "{%0,%1,%2,%3}, {%4,%5,%6,%7}, {%8,%9}, {%0,%1,%2,%3};"
                        : "+f"(acc[n][0]), "+f"(acc[n][1]), "+f"(acc[n][2]), "+f"(acc[n][3])
                        : "r"(Ah[0]), "r"(Ah[1]), "r"(Ah[2]), "r"(Ah[3]),
                          "r"(Bh[s][n][0]), "r"(Bh[s][n][1]));
                    asm volatile(
                        "mma.sync.aligned.m16n8k16.row.col.f32.f16.f16.f32 "
                        "{%0,%1,%2,%3}, {%4,%5,%6,%7}, {%8,%9}, {%0,%1,%2,%3};"
                        : "+f"(acc[n][0]), "+f"(acc[n][1]), "+f"(acc[n][2]), "+f"(acc[n][3])
                        : "r"(Ah[0]), "r"(Ah[1]), "r"(Ah[2]), "r"(Ah[3]),
                          "r"(Bl[s][n][0]), "r"(Bl[s][n][1]));
                    asm volatile(
                        "mma.sync.aligned.m16n8k16.row.col.f32.f16.f16.f32 "
                        "{%0,%1,%2,%3}, {%4,%5,%6,%7}, {%8,%9}, {%0,%1,%2,%3};"
                        : "+f"(acc[n][0]), "+f"(acc[n][1]), "+f"(acc[n][2]), "+f"(acc[n][3])
                        : "r"(Al[0]), "r"(Al[1]), "r"(Al[2]), "r"(Al[3]),
                          "r"(Bh[s][n][0]), "r"(Bh[s][n][1]));
                }
            }
        }

        // tanh
#pragma unroll
        for (int n = 0; n < 2; n++)
#pragma unroll
            for (int d = 0; d < 4; d++)
                v[n][d] = ftanh(acc[n][d]);

        // store h(t) hi/lo to buf t&1
        {
            char* ws = hbase + (t & 1) * (2 * HSEG16);
#pragma unroll
            for (int n = 0; n < 2; n++) {
                float h0 = __half2float(__float2half_rn(v[n][0]));
                float h1 = __half2float(__float2half_rn(v[n][1]));
                float h2 = __half2float(__float2half_rn(v[n][2]));
                float h3 = __half2float(__float2half_rn(v[n][3]));
                *(uint32_t*)(ws + stA[n])          = pkh(h0, h1);
                *(uint32_t*)(ws + HSEG16 + stA[n]) = pkh(v[n][0] - h0, v[n][1] - h1);
                *(uint32_t*)(ws + stB[n])          = pkh(h2, h3);
                *(uint32_t*)(ws + HSEG16 + stB[n]) = pkh(v[n][2] - h2, v[n][3] - h3);
            }
        }
        __syncthreads();
    }

    // ---- Dense(1) + sigmoid ----
    float pA = 0.f, pB = 0.f;
#pragma unroll
    for (int n = 0; n < 2; n++) {
        const float2 wd2 = *(const float2*)&Wd[wc * 16 + n * 8 + 2 * q];
        pA += v[n][0] * wd2.x + v[n][1] * wd2.y;
        pB += v[n][2] * wd2.x + v[n][3] * wd2.y;
    }
    pA += __shfl_xor_sync(0xffffffff, pA, 1);
    pA += __shfl_xor_sync(0xffffffff, pA, 2);
    pB += __shfl_xor_sync(0xffffffff, pB, 1);
    pB += __shfl_xor_sync(0xffffffff, pB, 2);
    if (q == 0) {
        red[rowA * 8 + wc] = pA;
        red[rowB * 8 + wc] = pB;
    }
    __syncthreads();
    if (tid < 16) {
        float s = bd[0];
#pragma unroll
        for (int c = 0; c < 8; c++) s += red[tid * 8 + c];
        out[b0 + tid] = __fdividef(1.f, 1.f + __expf(-s));
    }
}

// ---------------------------------------------------------------------------
extern "C" void kernel_launch(void* const* d_in, const int* in_sizes, int n_in,
                              void* d_out, int out_size) {
    const int*   x   = (const int*)d_in[0];
    const float* emb = (const float*)d_in[1];
    const float* Wxh = (const float*)d_in[2];
    const float* Whh = (const float*)d_in[3];
    const float* bh  = (const float*)d_in[4];
    const float* Wd  = (const float*)d_in[5];
    const float* bd  = (const float*)d_in[6];
    float* out = (float*)d_out;

    proj_kernel<<<(VOCAB + 127) / 128, 256>>>(emb, Wxh);

    const int smem = 65536 + 16 * SEQ * 4;   // 70656 B -> 2 blocks/SM
    cudaFuncSetAttribute(rnn_tc_kernel, cudaFuncAttributeMaxDynamicSharedMemorySize, smem);
    rnn_tc_kernel<<<BATCH / 16, 256, smem>>>(x, Whh, bh, Wd, bd, out);
}